// round 7
// baseline (speedup 1.0000x reference)
#include <cuda_runtime.h>
#include <cuda_fp16.h>
#include <math.h>

#define NN     50000
#define EE     800000
#define FIN    128
#define HID    32
#define HEADS  4
#define C1     128      // HEADS*HID
#define NCLS   16
#define NEG    0.2f
#define NEGINF_ORD 0x007FFFFFu   // f2o(-inf)

// ---------------- scratch (device globals; no allocation allowed) -----------
// NOTE: g_deg is zero on module load and re-zeroed by k_scanBC each call,
// so k_gemm1h's counting blocks can atomicAdd into it immediately.
__device__ __align__(16) __half   g_h1h [NN * C1];
__device__ __align__(16) float    g_als1[NN * HEADS];
__device__ __align__(16) float    g_ald1[NN * HEADS];
__device__ __align__(16) float    g_act [NN * C1];
__device__ __align__(16) __half   g_h2h [NN * NCLS];
__device__ __align__(16) float    g_als2[NN];
__device__ __align__(16) float    g_ald2[NN];
__device__ __align__(16) unsigned g_maxu1[4];
__device__ __align__(16) unsigned g_maxu2[4];
__device__ __align__(16) int      g_deg   [NN];
__device__ __align__(16) int      g_rowptr[NN + 1];
__device__ __align__(16) int      g_rank  [EE];
__device__ __align__(16) int      g_srcl  [EE];
__device__ __align__(16) int      g_btot  [64];

// ---------------- helpers ----------------------------------------------------
__device__ __forceinline__ float lrelu(float v) { return v > 0.f ? v : NEG * v; }

__device__ __forceinline__ unsigned f2o(float f) {
    unsigned u = __float_as_uint(f);
    return (u & 0x80000000u) ? ~u : (u | 0x80000000u);
}
__device__ __forceinline__ float o2f(unsigned u) {
    return (u & 0x80000000u) ? __uint_as_float(u & 0x7fffffffu)
                             : __uint_as_float(~u);
}

__device__ __forceinline__ void ldm_x4(unsigned& r0, unsigned& r1, unsigned& r2, unsigned& r3,
                                       unsigned addr) {
    asm volatile("ldmatrix.sync.aligned.m8n8.x4.shared.b16 {%0,%1,%2,%3}, [%4];"
                 : "=r"(r0), "=r"(r1), "=r"(r2), "=r"(r3) : "r"(addr));
}
__device__ __forceinline__ void ldm_x4t(unsigned& r0, unsigned& r1, unsigned& r2, unsigned& r3,
                                        unsigned addr) {
    asm volatile("ldmatrix.sync.aligned.m8n8.x4.trans.shared.b16 {%0,%1,%2,%3}, [%4];"
                 : "=r"(r0), "=r"(r1), "=r"(r2), "=r"(r3) : "r"(addr));
}
__device__ __forceinline__ void mma16816(float* c, const unsigned* a, unsigned b0, unsigned b1) {
    asm volatile("mma.sync.aligned.m16n8k16.row.col.f32.f16.f16.f32 "
                 "{%0,%1,%2,%3}, {%4,%5,%6,%7}, {%8,%9}, {%0,%1,%2,%3};"
                 : "+f"(c[0]), "+f"(c[1]), "+f"(c[2]), "+f"(c[3])
                 : "r"(a[0]), "r"(a[1]), "r"(a[2]), "r"(a[3]), "r"(b0), "r"(b1));
}

// ---------------- GEMM1 via HMMA + overlapped degree counting ----------------
// blocks [0,391): GEMM tile (128 nodes).  blocks [391,1173): count+rank x4.
#define XSTR 136   // padded half stride for conflict-free ldmatrix
#define GB1  391
__global__ void __launch_bounds__(256, 2) k_gemm1h(const float* __restrict__ x,
                        const float* __restrict__ W1,
                        const float* __restrict__ a_src, const float* __restrict__ a_dst,
                        const int* __restrict__ ei) {
    const int tid  = threadIdx.x;

    if (blockIdx.x >= GB1) {
        // degree counting + per-edge rank (g_deg pre-zeroed)
        int e0 = ((blockIdx.x - GB1) * 256 + tid) * 4;
        if (e0 < EE) {
            int4 d4 = *(const int4*)(ei + EE + e0);
            int4 r4;
            r4.x = atomicAdd(&g_deg[d4.x], 1);
            r4.y = atomicAdd(&g_deg[d4.y], 1);
            r4.z = atomicAdd(&g_deg[d4.z], 1);
            r4.w = atomicAdd(&g_deg[d4.w], 1);
            *(int4*)(g_rank + e0) = r4;
        }
        return;
    }

    // per-call init of the max cells (consumed by later launches)
    if (blockIdx.x == 0) {
        if (tid < 4)  g_maxu1[tid] = NEGINF_ORD;
        if (tid == 4) g_maxu2[0] = NEGINF_ORD;
    }

    extern __shared__ __half dsm[];
    __half* xs = dsm;                 // [128][XSTR]
    __half* ws = dsm + 128 * XSTR;    // [128][XSTR]

    const int lane = tid & 31;
    const int warp = tid >> 5;
    const int nb   = blockIdx.x * 128;
    const int g    = lane >> 2;
    const int tig  = lane & 3;

    for (int i = tid; i < 128 * 32; i += 256) {
        int r = i >> 5, q = i & 31;
        float4 v = (nb + r < NN) ? *(const float4*)(x + (size_t)(nb + r) * 128 + q * 4)
                                 : make_float4(0.f, 0.f, 0.f, 0.f);
        __half2* dst = (__half2*)(xs + r * XSTR + q * 4);
        dst[0] = __floats2half2_rn(v.x, v.y);
        dst[1] = __floats2half2_rn(v.z, v.w);
    }
    for (int i = tid; i < 128 * 32; i += 256) {
        int r = i >> 5, q = i & 31;
        float4 v = *(const float4*)(W1 + r * 128 + q * 4);
        __half2* dst = (__half2*)(ws + r * XSTR + q * 4);
        dst[0] = __floats2half2_rn(v.x, v.y);
        dst[1] = __floats2half2_rn(v.z, v.w);
    }
    __syncthreads();

    unsigned xs_u = (unsigned)__cvta_generic_to_shared(xs);
    unsigned ws_u = (unsigned)__cvta_generic_to_shared(ws);
    unsigned aaddr = xs_u + ((warp * 16 + (lane & 15)) * XSTR + (lane >> 4) * 8) * 2;
    unsigned baddr = ws_u + ((lane & 15) * XSTR + (lane >> 4) * 8) * 2;

    float c[16][4];
#pragma unroll
    for (int j = 0; j < 16; j++)
#pragma unroll
        for (int q = 0; q < 4; q++) c[j][q] = 0.f;

#pragma unroll
    for (int ks = 0; ks < 8; ks++) {
        unsigned a[4];
        ldm_x4(a[0], a[1], a[2], a[3], aaddr + ks * 32);
#pragma unroll
        for (int p = 0; p < 8; p++) {
            unsigned b0, b1, b2, b3;
            ldm_x4t(b0, b1, b2, b3, baddr + ks * (16 * XSTR * 2) + p * 32);
            mma16816(c[2 * p],     a, b0, b1);
            mma16816(c[2 * p + 1], a, b2, b3);
        }
    }

    int r0 = nb + warp * 16 + g;
    int r1 = r0 + 8;
    bool v0 = r0 < NN, v1 = r1 < NN;
    float ss0[4] = {0, 0, 0, 0}, sd0[4] = {0, 0, 0, 0};
    float ss1[4] = {0, 0, 0, 0}, sd1[4] = {0, 0, 0, 0};
#pragma unroll
    for (int j = 0; j < 16; j++) {
        int col = j * 8 + tig * 2;
        float a0 = a_src[col], a1 = a_src[col + 1];
        float d0 = a_dst[col], d1 = a_dst[col + 1];
        int h = j >> 2;
        ss0[h] += c[j][0] * a0 + c[j][1] * a1;
        sd0[h] += c[j][0] * d0 + c[j][1] * d1;
        ss1[h] += c[j][2] * a0 + c[j][3] * a1;
        sd1[h] += c[j][2] * d0 + c[j][3] * d1;
        if (v0) *(__half2*)(g_h1h + (size_t)r0 * 128 + col) = __floats2half2_rn(c[j][0], c[j][1]);
        if (v1) *(__half2*)(g_h1h + (size_t)r1 * 128 + col) = __floats2half2_rn(c[j][2], c[j][3]);
    }
#pragma unroll
    for (int o = 1; o <= 2; o <<= 1) {
#pragma unroll
        for (int h = 0; h < 4; h++) {
            ss0[h] += __shfl_xor_sync(0xffffffffu, ss0[h], o);
            sd0[h] += __shfl_xor_sync(0xffffffffu, sd0[h], o);
            ss1[h] += __shfl_xor_sync(0xffffffffu, ss1[h], o);
            sd1[h] += __shfl_xor_sync(0xffffffffu, sd1[h], o);
        }
    }
    if (tig == 0) {
        if (v0) {
#pragma unroll
            for (int h = 0; h < 4; h++) {
                g_als1[r0 * 4 + h] = ss0[h];
                g_ald1[r0 * 4 + h] = sd0[h];
            }
        }
        if (v1) {
#pragma unroll
            for (int h = 0; h < 4; h++) {
                g_als1[r1 * 4 + h] = ss1[h];
                g_ald1[r1 * 4 + h] = sd1[h];
            }
        }
    }
}

// ---------------- scanA: per-1024 local scan + als1 max-reduce ---------------
// blocks [0,49): scan.  blocks [49,54): max over als1 (needs gemm1h done).
__global__ void k_scanA() {
    if (blockIdx.x >= 49) {
        int t = (blockIdx.x - 49) * 1024 + threadIdx.x;   // 5120 threads
        float m0 = -1e30f, m1 = -1e30f, m2 = -1e30f, m3 = -1e30f;
        for (int n = t; n < NN; n += 5120) {
            float4 a = *(const float4*)(g_als1 + n * 4);
            m0 = fmaxf(m0, a.x); m1 = fmaxf(m1, a.y);
            m2 = fmaxf(m2, a.z); m3 = fmaxf(m3, a.w);
        }
#pragma unroll
        for (int o = 16; o >= 1; o >>= 1) {
            m0 = fmaxf(m0, __shfl_xor_sync(0xffffffffu, m0, o));
            m1 = fmaxf(m1, __shfl_xor_sync(0xffffffffu, m1, o));
            m2 = fmaxf(m2, __shfl_xor_sync(0xffffffffu, m2, o));
            m3 = fmaxf(m3, __shfl_xor_sync(0xffffffffu, m3, o));
        }
        if ((threadIdx.x & 31) == 0) {
            atomicMax(&g_maxu1[0], f2o(m0));
            atomicMax(&g_maxu1[1], f2o(m1));
            atomicMax(&g_maxu1[2], f2o(m2));
            atomicMax(&g_maxu1[3], f2o(m3));
        }
        return;
    }
    __shared__ int sw[32];
    int t = threadIdx.x, b = blockIdx.x;
    int i = b * 1024 + t;
    int v = (i < NN) ? g_deg[i] : 0;
    int x = v;
#pragma unroll
    for (int o = 1; o < 32; o <<= 1) {
        int y = __shfl_up_sync(0xffffffffu, x, o);
        if ((t & 31) >= o) x += y;
    }
    if ((t & 31) == 31) sw[t >> 5] = x;
    __syncthreads();
    if (t < 32) {
        int y = sw[t];
#pragma unroll
        for (int o = 1; o < 32; o <<= 1) {
            int z = __shfl_up_sync(0xffffffffu, y, o);
            if (t >= o) y += z;
        }
        sw[t] = y;
    }
    __syncthreads();
    int off = (t >= 32) ? sw[(t >> 5) - 1] : 0;
    int incl = x + off;
    if (i < NN) g_rowptr[i] = incl - v;     // block-local exclusive
    if (t == 1023) g_btot[b] = incl;
}

// ---------------- scanBC: add block offsets; re-zero g_deg for next call -----
__global__ void k_scanBC() {
    __shared__ int sh_boff[64];
    __shared__ int w0s;
    int t = threadIdx.x;
    int x = 0, v = 0;
    if (t < 64) {
        v = (t < 49) ? g_btot[t] : 0;
        x = v;
#pragma unroll
        for (int o = 1; o < 32; o <<= 1) {
            int y = __shfl_up_sync(0xffffffffu, x, o);
            if ((t & 31) >= o) x += y;
        }
        if (t == 31) w0s = x;
    }
    __syncthreads();
    if (t < 64) sh_boff[t] = (x + ((t >= 32) ? w0s : 0)) - v;
    __syncthreads();
    int i = blockIdx.x * 256 + t;
    if (i < NN) {
        g_rowptr[i] = g_rowptr[i] + sh_boff[i >> 10];
        g_deg[i] = 0;        // restore zeroed state for the next call's count
    }
    if (i == 0) g_rowptr[NN] = EE;
}

// ---------------- scatter src ids into CSR slots (rank-based, no atomics) ----
__global__ void k_scatter(const int* __restrict__ ei) {
    int e0 = (blockIdx.x * 256 + threadIdx.x) * 4;
    if (e0 >= EE) return;
    int4 s4 = *(const int4*)(ei + e0);
    int4 d4 = *(const int4*)(ei + EE + e0);
    int4 r4 = *(const int4*)(g_rank + e0);
    int p0 = __ldg(&g_rowptr[d4.x]) + r4.x;
    int p1 = __ldg(&g_rowptr[d4.y]) + r4.y;
    int p2 = __ldg(&g_rowptr[d4.z]) + r4.z;
    int p3 = __ldg(&g_rowptr[d4.w]) + r4.w;
    g_srcl[p0] = s4.x;
    g_srcl[p1] = s4.y;
    g_srcl[p2] = s4.z;
    g_srcl[p3] = s4.w;
}

// ---------------- layer-1 fused aggregation: warp per dst node ---------------
// h1 in fp16: 2 edges in flight per warp, 16 lanes x 8 channels each.
__global__ void __launch_bounds__(256) k_nodeagg1(const float* __restrict__ b1) {
    __shared__ int    s_src[8][32];
    __shared__ float4 s_ex [8][32];
    int wip  = threadIdx.x >> 5;
    int gw   = (blockIdx.x * 256 + threadIdx.x) >> 5;   // node id
    int lane = threadIdx.x & 31;
    int sub  = lane >> 4;
    int cl   = lane & 15;           // channel group: channels cl*8..cl*8+7
    int head = cl >> 2;

    float4 ald = *(const float4*)(g_ald1 + gw * 4);
    uint4 mu = *(const uint4*)g_maxu1;
    float4 m4;
    m4.x = lrelu(o2f(mu.x) + ald.x);
    m4.y = lrelu(o2f(mu.y) + ald.y);
    m4.z = lrelu(o2f(mu.z) + ald.z);
    m4.w = lrelu(o2f(mu.w) + ald.w);

    int start = g_rowptr[gw], end = g_rowptr[gw + 1];

    float4 den4 = make_float4(0.f, 0.f, 0.f, 0.f);
    float accA[8], accB[8];
#pragma unroll
    for (int j = 0; j < 8; j++) { accA[j] = 0.f; accB[j] = 0.f; }

    // self loop (sub 0 only)
    {
        float4 a = *(const float4*)(g_als1 + gw * 4);
        float4 e4;
        e4.x = __expf(lrelu(a.x + ald.x) - m4.x);
        e4.y = __expf(lrelu(a.y + ald.y) - m4.y);
        e4.z = __expf(lrelu(a.z + ald.z) - m4.z);
        e4.w = __expf(lrelu(a.w + ald.w) - m4.w);
        if (lane == 0) den4 = e4;
        if (sub == 0) {
            float ex = head == 0 ? e4.x : head == 1 ? e4.y : head == 2 ? e4.z : e4.w;
            uint4 u = *(const uint4*)(g_h1h + (size_t)gw * 128 + cl * 8);
            const __half2* hp = (const __half2*)&u;
#pragma unroll
            for (int q = 0; q < 4; q++) {
                float2 f = __half22float2(hp[q]);
                accA[q * 2]     = ex * f.x;
                accA[q * 2 + 1] = ex * f.y;
            }
        }
    }

    for (int j0 = start; j0 < end; j0 += 32) {
        int idx = j0 + lane;
        bool val = idx < end;
        int s = val ? g_srcl[idx] : 0;
        float4 e4 = make_float4(0.f, 0.f, 0.f, 0.f);
        if (val) {
            float4 a = *(const float4*)(g_als1 + s * 4);
            e4.x = __expf(lrelu(a.x + ald.x) - m4.x);
            e4.y = __expf(lrelu(a.y + ald.y) - m4.y);
            e4.z = __expf(lrelu(a.z + ald.z) - m4.z);
            e4.w = __expf(lrelu(a.w + ald.w) - m4.w);
            den4.x += e4.x; den4.y += e4.y; den4.z += e4.z; den4.w += e4.w;
        }
        s_src[wip][lane] = s;
        s_ex [wip][lane] = e4;
        __syncwarp();
        int cnt = min(32, end - j0);
        int t = 0;
        for (; t + 4 <= cnt; t += 4) {
            int iA = t + sub, iB = t + 2 + sub;
            int sA = s_src[wip][iA], sB = s_src[wip][iB];
            float eA = ((const float*)&s_ex[wip][iA])[head];
            float eB = ((const float*)&s_ex[wip][iB])[head];
            uint4 uA = *(const uint4*)(g_h1h + (size_t)sA * 128 + cl * 8);
            uint4 uB = *(const uint4*)(g_h1h + (size_t)sB * 128 + cl * 8);
            const __half2* hA = (const __half2*)&uA;
            const __half2* hB = (const __half2*)&uB;
#pragma unroll
            for (int q = 0; q < 4; q++) {
                float2 fA = __half22float2(hA[q]);
                float2 fB = __half22float2(hB[q]);
                accA[q * 2]     = fmaf(eA, fA.x, accA[q * 2]);
                accA[q * 2 + 1] = fmaf(eA, fA.y, accA[q * 2 + 1]);
                accB[q * 2]     = fmaf(eB, fB.x, accB[q * 2]);
                accB[q * 2 + 1] = fmaf(eB, fB.y, accB[q * 2 + 1]);
            }
        }
        for (; t < cnt; t += 2) {
            int i = t + sub;
            if (i < cnt) {
                int sA = s_src[wip][i];
                float eA = ((const float*)&s_ex[wip][i])[head];
                uint4 uA = *(const uint4*)(g_h1h + (size_t)sA * 128 + cl * 8);
                const __half2* hA = (const __half2*)&uA;
#pragma unroll
                for (int q = 0; q < 4; q++) {
                    float2 fA = __half22float2(hA[q]);
                    accA[q * 2]     = fmaf(eA, fA.x, accA[q * 2]);
                    accA[q * 2 + 1] = fmaf(eA, fA.y, accA[q * 2 + 1]);
                }
            }
        }
        __syncwarp();
    }

#pragma unroll
    for (int j = 0; j < 8; j++) {
        accA[j] += accB[j];
        accA[j] += __shfl_xor_sync(0xffffffffu, accA[j], 16);
    }
#pragma unroll
    for (int o = 16; o >= 1; o >>= 1) {
        den4.x += __shfl_xor_sync(0xffffffffu, den4.x, o);
        den4.y += __shfl_xor_sync(0xffffffffu, den4.y, o);
        den4.z += __shfl_xor_sync(0xffffffffu, den4.z, o);
        den4.w += __shfl_xor_sync(0xffffffffu, den4.w, o);
    }
    if (sub == 0) {
        float den = head == 0 ? den4.x : head == 1 ? den4.y : head == 2 ? den4.z : den4.w;
        float inv = 1.f / den;
        float4 ba = ((const float4*)b1)[cl * 2];
        float4 bb = ((const float4*)b1)[cl * 2 + 1];
        float4 r0, r1;
        r0.x = accA[0] * inv + ba.x;  r0.x = r0.x > 0.f ? r0.x : expm1f(r0.x);
        r0.y = accA[1] * inv + ba.y;  r0.y = r0.y > 0.f ? r0.y : expm1f(r0.y);
        r0.z = accA[2] * inv + ba.z;  r0.z = r0.z > 0.f ? r0.z : expm1f(r0.z);
        r0.w = accA[3] * inv + ba.w;  r0.w = r0.w > 0.f ? r0.w : expm1f(r0.w);
        r1.x = accA[4] * inv + bb.x;  r1.x = r1.x > 0.f ? r1.x : expm1f(r1.x);
        r1.y = accA[5] * inv + bb.y;  r1.y = r1.y > 0.f ? r1.y : expm1f(r1.y);
        r1.z = accA[6] * inv + bb.z;  r1.z = r1.z > 0.f ? r1.z : expm1f(r1.z);
        r1.w = accA[7] * inv + bb.w;  r1.w = r1.w > 0.f ? r1.w : expm1f(r1.w);
        *(float4*)(g_act + (size_t)gw * 128 + cl * 8)     = r0;
        *(float4*)(g_act + (size_t)gw * 128 + cl * 8 + 4) = r1;
    }
}

// ---------------- GEMM2: h2h = fp16(act @ W2) ; als2/ald2 + global max -------
__global__ void k_gemm2(const float* __restrict__ W2, const float* __restrict__ a_src2,
                        const float* __restrict__ a_dst2) {
    __shared__ float w2s[128 * 16];
    __shared__ float xs[16][129];
    __shared__ float s_ps[16];
    const int tid = threadIdx.x;
    const int nb  = blockIdx.x * 16;
    for (int i = tid; i < 2048; i += 256) w2s[i] = W2[i];
    for (int i = tid; i < 2048; i += 256) {
        int n = i >> 7, k = i & 127;
        xs[n][k] = g_act[(nb + n) * 128 + k];
    }
    __syncthreads();
    int nl = tid >> 4, c = tid & 15;
    float acc = 0.f;
#pragma unroll 8
    for (int k = 0; k < 128; k++) acc = fmaf(xs[nl][k], w2s[k * 16 + c], acc);
    int n = nb + nl;
    g_h2h[n * 16 + c] = __float2half_rn(acc);
    float ps = acc * a_src2[c], pd = acc * a_dst2[c];
#pragma unroll
    for (int m = 8; m >= 1; m >>= 1) {
        ps += __shfl_xor_sync(0xffffffffu, ps, m, 16);
        pd += __shfl_xor_sync(0xffffffffu, pd, m, 16);
    }
    if (c == 0) {
        g_als2[n] = ps; g_ald2[n] = pd;
        s_ps[nl] = ps;
    }
    __syncthreads();
    if (tid == 0) {
        float m = s_ps[0];
#pragma unroll
        for (int i = 1; i < 16; i++) m = fmaxf(m, s_ps[i]);
        atomicMax(&g_maxu2[0], f2o(m));
    }
}

// ---------------- layer-2 fused aggregation + log_softmax --------------------
// 4 edges in flight: 4 subs x 8 lanes; lane covers 2 classes (half2).
__global__ void __launch_bounds__(256) k_nodeagg2(const float* __restrict__ b2,
                                                  float* __restrict__ out) {
    __shared__ float s_ex2[8][32];
    __shared__ int   s_s2 [8][32];
    int wip  = threadIdx.x >> 5;
    int gw   = (blockIdx.x * 256 + threadIdx.x) >> 5;
    int lane = threadIdx.x & 31;
    int sub  = lane >> 3, cl = lane & 7;

    float ald = g_ald2[gw];
    float m = lrelu(o2f(g_maxu2[0]) + ald);
    int start = g_rowptr[gw], end = g_rowptr[gw + 1];

    float2 accA = make_float2(0.f, 0.f), accB = make_float2(0.f, 0.f);
    float den_l = 0.f;

    // self loop
    {
        float exs = __expf(lrelu(g_als2[gw] + ald) - m);
        if (lane == 0) den_l = exs;
        if (sub == 0) {
            float2 f = __half22float2(*(const __half2*)(g_h2h + (size_t)gw * 16 + cl * 2));
            accA.x = exs * f.x;
            accA.y = exs * f.y;
        }
    }

    for (int j0 = start; j0 < end; j0 += 32) {
        int idx = j0 + lane;
        bool val = idx < end;
        int s = val ? g_srcl[idx] : 0;
        float e = 0.f;
        if (val) {
            e = __expf(lrelu(g_als2[s] + ald) - m);
            den_l += e;
        }
        s_s2 [wip][lane] = s;
        s_ex2[wip][lane] = e;
        __syncwarp();
        int cnt = min(32, end - j0);
        for (int t = 0; t < cnt; t += 8) {
            int iA = t + sub, iB = t + 4 + sub;
            if (iA < cnt) {
                int   sA = s_s2 [wip][iA];
                float eA = s_ex2[wip][iA];
                float2 f = __half22float2(*(const __half2*)(g_h2h + (size_t)sA * 16 + cl * 2));
                accA.x = fmaf(eA, f.x, accA.x);
                accA.y = fmaf(eA, f.y, accA.y);
            }
            if (iB < cnt) {
                int   sB = s_s2 [wip][iB];
                float eB = s_ex2[wip][iB];
                float2 f = __half22float2(*(const __half2*)(g_h2h + (size_t)sB * 16 + cl * 2));
                accB.x = fmaf(eB, f.x, accB.x);
                accB.y = fmaf(eB, f.y, accB.y);
            }
        }
        __syncwarp();
    }
    accA.x += accB.x; accA.y += accB.y;
    accA.x += __shfl_xor_sync(0xffffffffu, accA.x, 8);
    accA.y += __shfl_xor_sync(0xffffffffu, accA.y, 8);
    accA.x += __shfl_xor_sync(0xffffffffu, accA.x, 16);
    accA.y += __shfl_xor_sync(0xffffffffu, accA.y, 16);
#pragma unroll
    for (int o = 16; o >= 1; o >>= 1) den_l += __shfl_xor_sync(0xffffffffu, den_l, o);

    float inv = 1.f / den_l;
    float v0 = accA.x * inv + b2[cl * 2];
    float v1 = accA.y * inv + b2[cl * 2 + 1];
    float mx = fmaxf(v0, v1);
#pragma unroll
    for (int o = 4; o >= 1; o >>= 1) mx = fmaxf(mx, __shfl_xor_sync(0xffffffffu, mx, o, 8));
    float s = __expf(v0 - mx) + __expf(v1 - mx);
#pragma unroll
    for (int o = 4; o >= 1; o >>= 1) s += __shfl_xor_sync(0xffffffffu, s, o, 8);
    if (sub == 0) {
        float ls = logf(s);
        float2 r = make_float2(v0 - mx - ls, v1 - mx - ls);
        *(float2*)(out + (size_t)gw * 16 + cl * 2) = r;
    }
}

// ---------------- launch ------------------------------------------------------
extern "C" void kernel_launch(void* const* d_in, const int* in_sizes, int n_in,
                              void* d_out, int out_size) {
    const float* x      = (const float*)d_in[0];
    const int*   ei     = (const int*)  d_in[1];
    const float* W1     = (const float*)d_in[2];
    const float* a_src1 = (const float*)d_in[3];
    const float* a_dst1 = (const float*)d_in[4];
    const float* b1     = (const float*)d_in[5];
    const float* W2     = (const float*)d_in[6];
    const float* a_src2 = (const float*)d_in[7];
    const float* a_dst2 = (const float*)d_in[8];
    const float* b2     = (const float*)d_in[9];
    float* out = (float*)d_out;

    const int smem1 = 2 * 128 * XSTR * sizeof(__half);   // 69632
    cudaFuncSetAttribute(k_gemm1h, cudaFuncAttributeMaxDynamicSharedMemorySize, smem1);

    k_gemm1h  <<<GB1 + 782, 256, smem1>>>(x, W1, a_src1, a_dst1, ei);
    k_scanA   <<<54, 1024>>>();
    k_scanBC  <<<196, 256>>>();
    k_scatter <<<782, 256>>>(ei);
    k_nodeagg1<<<6250, 256>>>(b1);
    k_gemm2   <<<3125, 256>>>(W2, a_src2, a_dst2);
    k_nodeagg2<<<6250, 256>>>(b2, out);
}

// round 8
// speedup vs baseline: 1.0373x; 1.0373x over previous
#include <cuda_runtime.h>
#include <cuda_fp16.h>
#include <math.h>

#define NN     50000
#define EE     800000
#define FIN    128
#define HID    32
#define HEADS  4
#define C1     128      // HEADS*HID
#define NCLS   16
#define NEG    0.2f
#define NEGINF_ORD 0x007FFFFFu   // f2o(-inf)

// ---------------- scratch (device globals; no allocation allowed) -----------
// NOTE: g_deg is zero on module load and re-zeroed by k_scanBC each call,
// so k_gemm1h's counting blocks can atomicAdd into it immediately.
__device__ __align__(16) __half   g_h1h [NN * C1];
__device__ __align__(16) float    g_als1[NN * HEADS];
__device__ __align__(16) float    g_ald1[NN * HEADS];
__device__ __align__(16) float    g_act [NN * C1];
__device__ __align__(16) __half   g_h2h [NN * NCLS];
__device__ __align__(16) float    g_als2[NN];
__device__ __align__(16) float    g_ald2[NN];
__device__ __align__(16) unsigned g_maxu1[4];
__device__ __align__(16) unsigned g_maxu2[4];
__device__ __align__(16) int      g_deg   [NN];
__device__ __align__(16) int      g_rowptr[NN + 1];
__device__ __align__(16) int      g_rank  [EE];
__device__ __align__(16) int      g_srcl  [EE];
__device__ __align__(16) int      g_btot  [64];

// ---------------- helpers ----------------------------------------------------
__device__ __forceinline__ float lrelu(float v) { return v > 0.f ? v : NEG * v; }

__device__ __forceinline__ unsigned f2o(float f) {
    unsigned u = __float_as_uint(f);
    return (u & 0x80000000u) ? ~u : (u | 0x80000000u);
}
__device__ __forceinline__ float o2f(unsigned u) {
    return (u & 0x80000000u) ? __uint_as_float(u & 0x7fffffffu)
                             : __uint_as_float(~u);
}

__device__ __forceinline__ void ldm_x4(unsigned& r0, unsigned& r1, unsigned& r2, unsigned& r3,
                                       unsigned addr) {
    asm volatile("ldmatrix.sync.aligned.m8n8.x4.shared.b16 {%0,%1,%2,%3}, [%4];"
                 : "=r"(r0), "=r"(r1), "=r"(r2), "=r"(r3) : "r"(addr));
}
__device__ __forceinline__ void ldm_x4t(unsigned& r0, unsigned& r1, unsigned& r2, unsigned& r3,
                                        unsigned addr) {
    asm volatile("ldmatrix.sync.aligned.m8n8.x4.trans.shared.b16 {%0,%1,%2,%3}, [%4];"
                 : "=r"(r0), "=r"(r1), "=r"(r2), "=r"(r3) : "r"(addr));
}
__device__ __forceinline__ void mma16816(float* c, const unsigned* a, unsigned b0, unsigned b1) {
    asm volatile("mma.sync.aligned.m16n8k16.row.col.f32.f16.f16.f32 "
                 "{%0,%1,%2,%3}, {%4,%5,%6,%7}, {%8,%9}, {%0,%1,%2,%3};"
                 : "+f"(c[0]), "+f"(c[1]), "+f"(c[2]), "+f"(c[3])
                 : "r"(a[0]), "r"(a[1]), "r"(a[2]), "r"(a[3]), "r"(b0), "r"(b1));
}

// ---------------- GEMM1 via HMMA + overlapped degree counting ----------------
// blocks [0,391): GEMM tile (128 nodes).  blocks [391,1173): count+rank x4.
#define XSTR 136   // padded half stride for conflict-free ldmatrix
#define GB1  391
__global__ void __launch_bounds__(256, 2) k_gemm1h(const float* __restrict__ x,
                        const float* __restrict__ W1,
                        const float* __restrict__ a_src, const float* __restrict__ a_dst,
                        const int* __restrict__ ei) {
    const int tid  = threadIdx.x;

    if (blockIdx.x >= GB1) {
        // degree counting + per-edge rank (g_deg pre-zeroed)
        int e0 = ((blockIdx.x - GB1) * 256 + tid) * 4;
        if (e0 < EE) {
            int4 d4 = *(const int4*)(ei + EE + e0);
            int4 r4;
            r4.x = atomicAdd(&g_deg[d4.x], 1);
            r4.y = atomicAdd(&g_deg[d4.y], 1);
            r4.z = atomicAdd(&g_deg[d4.z], 1);
            r4.w = atomicAdd(&g_deg[d4.w], 1);
            *(int4*)(g_rank + e0) = r4;
        }
        return;
    }

    // per-call init of the max cells (consumed by later launches)
    if (blockIdx.x == 0) {
        if (tid < 4)  g_maxu1[tid] = NEGINF_ORD;
        if (tid == 4) g_maxu2[0] = NEGINF_ORD;
    }

    extern __shared__ __half dsm[];
    __half* xs = dsm;                 // [128][XSTR]
    __half* ws = dsm + 128 * XSTR;    // [128][XSTR]

    const int lane = tid & 31;
    const int warp = tid >> 5;
    const int nb   = blockIdx.x * 128;
    const int g    = lane >> 2;
    const int tig  = lane & 3;

    for (int i = tid; i < 128 * 32; i += 256) {
        int r = i >> 5, q = i & 31;
        float4 v = (nb + r < NN) ? *(const float4*)(x + (size_t)(nb + r) * 128 + q * 4)
                                 : make_float4(0.f, 0.f, 0.f, 0.f);
        __half2* dst = (__half2*)(xs + r * XSTR + q * 4);
        dst[0] = __floats2half2_rn(v.x, v.y);
        dst[1] = __floats2half2_rn(v.z, v.w);
    }
    for (int i = tid; i < 128 * 32; i += 256) {
        int r = i >> 5, q = i & 31;
        float4 v = *(const float4*)(W1 + r * 128 + q * 4);
        __half2* dst = (__half2*)(ws + r * XSTR + q * 4);
        dst[0] = __floats2half2_rn(v.x, v.y);
        dst[1] = __floats2half2_rn(v.z, v.w);
    }
    __syncthreads();

    unsigned xs_u = (unsigned)__cvta_generic_to_shared(xs);
    unsigned ws_u = (unsigned)__cvta_generic_to_shared(ws);
    unsigned aaddr = xs_u + ((warp * 16 + (lane & 15)) * XSTR + (lane >> 4) * 8) * 2;
    unsigned baddr = ws_u + ((lane & 15) * XSTR + (lane >> 4) * 8) * 2;

    float c[16][4];
#pragma unroll
    for (int j = 0; j < 16; j++)
#pragma unroll
        for (int q = 0; q < 4; q++) c[j][q] = 0.f;

#pragma unroll
    for (int ks = 0; ks < 8; ks++) {
        unsigned a[4];
        ldm_x4(a[0], a[1], a[2], a[3], aaddr + ks * 32);
#pragma unroll
        for (int p = 0; p < 8; p++) {
            unsigned b0, b1, b2, b3;
            ldm_x4t(b0, b1, b2, b3, baddr + ks * (16 * XSTR * 2) + p * 32);
            mma16816(c[2 * p],     a, b0, b1);
            mma16816(c[2 * p + 1], a, b2, b3);
        }
    }

    int r0 = nb + warp * 16 + g;
    int r1 = r0 + 8;
    bool v0 = r0 < NN, v1 = r1 < NN;
    float ss0[4] = {0, 0, 0, 0}, sd0[4] = {0, 0, 0, 0};
    float ss1[4] = {0, 0, 0, 0}, sd1[4] = {0, 0, 0, 0};
#pragma unroll
    for (int j = 0; j < 16; j++) {
        int col = j * 8 + tig * 2;
        float a0 = a_src[col], a1 = a_src[col + 1];
        float d0 = a_dst[col], d1 = a_dst[col + 1];
        int h = j >> 2;
        ss0[h] += c[j][0] * a0 + c[j][1] * a1;
        sd0[h] += c[j][0] * d0 + c[j][1] * d1;
        ss1[h] += c[j][2] * a0 + c[j][3] * a1;
        sd1[h] += c[j][2] * d0 + c[j][3] * d1;
        if (v0) *(__half2*)(g_h1h + (size_t)r0 * 128 + col) = __floats2half2_rn(c[j][0], c[j][1]);
        if (v1) *(__half2*)(g_h1h + (size_t)r1 * 128 + col) = __floats2half2_rn(c[j][2], c[j][3]);
    }
#pragma unroll
    for (int o = 1; o <= 2; o <<= 1) {
#pragma unroll
        for (int h = 0; h < 4; h++) {
            ss0[h] += __shfl_xor_sync(0xffffffffu, ss0[h], o);
            sd0[h] += __shfl_xor_sync(0xffffffffu, sd0[h], o);
            ss1[h] += __shfl_xor_sync(0xffffffffu, ss1[h], o);
            sd1[h] += __shfl_xor_sync(0xffffffffu, sd1[h], o);
        }
    }
    if (tig == 0) {
        if (v0) {
#pragma unroll
            for (int h = 0; h < 4; h++) {
                g_als1[r0 * 4 + h] = ss0[h];
                g_ald1[r0 * 4 + h] = sd0[h];
            }
        }
        if (v1) {
#pragma unroll
            for (int h = 0; h < 4; h++) {
                g_als1[r1 * 4 + h] = ss1[h];
                g_ald1[r1 * 4 + h] = sd1[h];
            }
        }
    }
}

// ---------------- scanA: per-1024 local scan + als1 max-reduce ---------------
// blocks [0,49): scan.  blocks [49,54): max over als1 (needs gemm1h done).
__global__ void k_scanA() {
    if (blockIdx.x >= 49) {
        int t = (blockIdx.x - 49) * 1024 + threadIdx.x;   // 5120 threads
        float m0 = -1e30f, m1 = -1e30f, m2 = -1e30f, m3 = -1e30f;
        for (int n = t; n < NN; n += 5120) {
            float4 a = *(const float4*)(g_als1 + n * 4);
            m0 = fmaxf(m0, a.x); m1 = fmaxf(m1, a.y);
            m2 = fmaxf(m2, a.z); m3 = fmaxf(m3, a.w);
        }
#pragma unroll
        for (int o = 16; o >= 1; o >>= 1) {
            m0 = fmaxf(m0, __shfl_xor_sync(0xffffffffu, m0, o));
            m1 = fmaxf(m1, __shfl_xor_sync(0xffffffffu, m1, o));
            m2 = fmaxf(m2, __shfl_xor_sync(0xffffffffu, m2, o));
            m3 = fmaxf(m3, __shfl_xor_sync(0xffffffffu, m3, o));
        }
        if ((threadIdx.x & 31) == 0) {
            atomicMax(&g_maxu1[0], f2o(m0));
            atomicMax(&g_maxu1[1], f2o(m1));
            atomicMax(&g_maxu1[2], f2o(m2));
            atomicMax(&g_maxu1[3], f2o(m3));
        }
        return;
    }
    __shared__ int sw[32];
    int t = threadIdx.x, b = blockIdx.x;
    int i = b * 1024 + t;
    int v = (i < NN) ? g_deg[i] : 0;
    int x = v;
#pragma unroll
    for (int o = 1; o < 32; o <<= 1) {
        int y = __shfl_up_sync(0xffffffffu, x, o);
        if ((t & 31) >= o) x += y;
    }
    if ((t & 31) == 31) sw[t >> 5] = x;
    __syncthreads();
    if (t < 32) {
        int y = sw[t];
#pragma unroll
        for (int o = 1; o < 32; o <<= 1) {
            int z = __shfl_up_sync(0xffffffffu, y, o);
            if (t >= o) y += z;
        }
        sw[t] = y;
    }
    __syncthreads();
    int off = (t >= 32) ? sw[(t >> 5) - 1] : 0;
    int incl = x + off;
    if (i < NN) g_rowptr[i] = incl - v;     // block-local exclusive
    if (t == 1023) g_btot[b] = incl;
}

// ---------------- scanBC: add block offsets; re-zero g_deg for next call -----
__global__ void k_scanBC() {
    __shared__ int sh_boff[64];
    __shared__ int w0s;
    int t = threadIdx.x;
    int x = 0, v = 0;
    if (t < 64) {
        v = (t < 49) ? g_btot[t] : 0;
        x = v;
#pragma unroll
        for (int o = 1; o < 32; o <<= 1) {
            int y = __shfl_up_sync(0xffffffffu, x, o);
            if ((t & 31) >= o) x += y;
        }
        if (t == 31) w0s = x;
    }
    __syncthreads();
    if (t < 64) sh_boff[t] = (x + ((t >= 32) ? w0s : 0)) - v;
    __syncthreads();
    int i = blockIdx.x * 256 + t;
    if (i < NN) {
        g_rowptr[i] = g_rowptr[i] + sh_boff[i >> 10];
        g_deg[i] = 0;        // restore zeroed state for the next call's count
    }
    if (i == 0) g_rowptr[NN] = EE;
}

// ---------------- scatter src ids into CSR slots (rank-based, no atomics) ----
__global__ void k_scatter(const int* __restrict__ ei) {
    int e0 = (blockIdx.x * 256 + threadIdx.x) * 4;
    if (e0 >= EE) return;
    int4 s4 = *(const int4*)(ei + e0);
    int4 d4 = *(const int4*)(ei + EE + e0);
    int4 r4 = *(const int4*)(g_rank + e0);
    int p0 = __ldg(&g_rowptr[d4.x]) + r4.x;
    int p1 = __ldg(&g_rowptr[d4.y]) + r4.y;
    int p2 = __ldg(&g_rowptr[d4.z]) + r4.z;
    int p3 = __ldg(&g_rowptr[d4.w]) + r4.w;
    g_srcl[p0] = s4.x;
    g_srcl[p1] = s4.y;
    g_srcl[p2] = s4.z;
    g_srcl[p3] = s4.w;
}

// ---------------- layer-1 fused aggregation: warp per dst node ---------------
// shfl-broadcast src ids; each lane computes exp for its own head; als and h
// gathers issue concurrently (no smem staging, no syncwarp).
__global__ void __launch_bounds__(256) k_nodeagg1(const float* __restrict__ b1) {
    int gw   = (blockIdx.x * 256 + threadIdx.x) >> 5;   // node id
    int lane = threadIdx.x & 31;
    int sub  = lane >> 4;           // 2 edge slots
    int cl   = lane & 15;           // channel group: channels cl*8..cl*8+7
    int head = cl >> 2;

    float4 ald4 = *(const float4*)(g_ald1 + gw * 4);
    uint4 mu = *(const uint4*)g_maxu1;
    float ald_h = ((const float*)&ald4)[head];
    float m_h = lrelu(o2f(((const unsigned*)&mu)[head]) + ald_h);

    int start = g_rowptr[gw], end = g_rowptr[gw + 1];

    float den_l = 0.f;
    float accA[8], accB[8];
#pragma unroll
    for (int j = 0; j < 8; j++) { accA[j] = 0.f; accB[j] = 0.f; }

    // self loop
    {
        float a_h = __ldg(g_als1 + gw * 4 + head);
        float ex = __expf(lrelu(a_h + ald_h) - m_h);
        if (sub == 0 && (cl & 3) == 0) den_l = ex;
        if (sub == 0) {
            uint4 u = *(const uint4*)(g_h1h + (size_t)gw * 128 + cl * 8);
            const __half2* hp = (const __half2*)&u;
#pragma unroll
            for (int q = 0; q < 4; q++) {
                float2 f = __half22float2(hp[q]);
                accA[q * 2]     = ex * f.x;
                accA[q * 2 + 1] = ex * f.y;
            }
        }
    }

    for (int j0 = start; j0 < end; j0 += 32) {
        int idx = j0 + lane;
        int s = (idx < end) ? g_srcl[idx] : 0;
        int cnt = min(32, end - j0);
        for (int t = 0; t < cnt; t += 4) {
            int iA = t + sub, iB = t + 2 + sub;
            int sA = __shfl_sync(0xffffffffu, s, iA);
            int sB = __shfl_sync(0xffffffffu, s, iB);
            if (iA < cnt) {
                float aA = __ldg(g_als1 + sA * 4 + head);
                uint4 uA = *(const uint4*)(g_h1h + (size_t)sA * 128 + cl * 8);
                float eA = __expf(lrelu(aA + ald_h) - m_h);
                if ((cl & 3) == 0) den_l += eA;
                const __half2* hA = (const __half2*)&uA;
#pragma unroll
                for (int q = 0; q < 4; q++) {
                    float2 fA = __half22float2(hA[q]);
                    accA[q * 2]     = fmaf(eA, fA.x, accA[q * 2]);
                    accA[q * 2 + 1] = fmaf(eA, fA.y, accA[q * 2 + 1]);
                }
            }
            if (iB < cnt) {
                float aB = __ldg(g_als1 + sB * 4 + head);
                uint4 uB = *(const uint4*)(g_h1h + (size_t)sB * 128 + cl * 8);
                float eB = __expf(lrelu(aB + ald_h) - m_h);
                if ((cl & 3) == 0) den_l += eB;
                const __half2* hB = (const __half2*)&uB;
#pragma unroll
                for (int q = 0; q < 4; q++) {
                    float2 fB = __half22float2(hB[q]);
                    accB[q * 2]     = fmaf(eB, fB.x, accB[q * 2]);
                    accB[q * 2 + 1] = fmaf(eB, fB.y, accB[q * 2 + 1]);
                }
            }
        }
    }

#pragma unroll
    for (int j = 0; j < 8; j++) {
        accA[j] += accB[j];
        accA[j] += __shfl_xor_sync(0xffffffffu, accA[j], 16);
    }
    // den: designated lanes (cl&3)==0 hold per-head partial; combine subs,
    // then broadcast within each 16-lane half from lane (cl&12).
    den_l += __shfl_xor_sync(0xffffffffu, den_l, 16);
    float den = __shfl_sync(0xffffffffu, den_l, cl & 12, 16);

    if (sub == 0) {
        float inv = 1.f / den;
        float4 ba = ((const float4*)b1)[cl * 2];
        float4 bb = ((const float4*)b1)[cl * 2 + 1];
        float4 r0, r1;
        r0.x = accA[0] * inv + ba.x;  r0.x = r0.x > 0.f ? r0.x : expm1f(r0.x);
        r0.y = accA[1] * inv + ba.y;  r0.y = r0.y > 0.f ? r0.y : expm1f(r0.y);
        r0.z = accA[2] * inv + ba.z;  r0.z = r0.z > 0.f ? r0.z : expm1f(r0.z);
        r0.w = accA[3] * inv + ba.w;  r0.w = r0.w > 0.f ? r0.w : expm1f(r0.w);
        r1.x = accA[4] * inv + bb.x;  r1.x = r1.x > 0.f ? r1.x : expm1f(r1.x);
        r1.y = accA[5] * inv + bb.y;  r1.y = r1.y > 0.f ? r1.y : expm1f(r1.y);
        r1.z = accA[6] * inv + bb.z;  r1.z = r1.z > 0.f ? r1.z : expm1f(r1.z);
        r1.w = accA[7] * inv + bb.w;  r1.w = r1.w > 0.f ? r1.w : expm1f(r1.w);
        *(float4*)(g_act + (size_t)gw * 128 + cl * 8)     = r0;
        *(float4*)(g_act + (size_t)gw * 128 + cl * 8 + 4) = r1;
    }
}

// ---------------- GEMM2: h2h = fp16(act @ W2) ; als2/ald2 + global max -------
__global__ void k_gemm2(const float* __restrict__ W2, const float* __restrict__ a_src2,
                        const float* __restrict__ a_dst2) {
    __shared__ float w2s[128 * 16];
    __shared__ float xs[16][129];
    __shared__ float s_ps[16];
    const int tid = threadIdx.x;
    const int nb  = blockIdx.x * 16;
    for (int i = tid; i < 2048; i += 256) w2s[i] = W2[i];
    for (int i = tid; i < 2048; i += 256) {
        int n = i >> 7, k = i & 127;
        xs[n][k] = g_act[(nb + n) * 128 + k];
    }
    __syncthreads();
    int nl = tid >> 4, c = tid & 15;
    float acc = 0.f;
#pragma unroll 8
    for (int k = 0; k < 128; k++) acc = fmaf(xs[nl][k], w2s[k * 16 + c], acc);
    int n = nb + nl;
    g_h2h[n * 16 + c] = __float2half_rn(acc);
    float ps = acc * a_src2[c], pd = acc * a_dst2[c];
#pragma unroll
    for (int m = 8; m >= 1; m >>= 1) {
        ps += __shfl_xor_sync(0xffffffffu, ps, m, 16);
        pd += __shfl_xor_sync(0xffffffffu, pd, m, 16);
    }
    if (c == 0) {
        g_als2[n] = ps; g_ald2[n] = pd;
        s_ps[nl] = ps;
    }
    __syncthreads();
    if (tid == 0) {
        float m = s_ps[0];
#pragma unroll
        for (int i = 1; i < 16; i++) m = fmaxf(m, s_ps[i]);
        atomicMax(&g_maxu2[0], f2o(m));
    }
}

// ---------------- layer-2 fused aggregation + log_softmax --------------------
// shfl-broadcast src ids; per-lane exp; 4 edges in flight (4 subs x 8 lanes).
__global__ void __launch_bounds__(256) k_nodeagg2(const float* __restrict__ b2,
                                                  float* __restrict__ out) {
    int gw   = (blockIdx.x * 256 + threadIdx.x) >> 5;
    int lane = threadIdx.x & 31;
    int sub  = lane >> 3, cl = lane & 7;

    float ald = g_ald2[gw];
    float m = lrelu(o2f(g_maxu2[0]) + ald);
    int start = g_rowptr[gw], end = g_rowptr[gw + 1];

    float2 accA = make_float2(0.f, 0.f), accB = make_float2(0.f, 0.f);
    float den_l = 0.f;

    // self loop
    {
        float exs = __expf(lrelu(__ldg(g_als2 + gw) + ald) - m);
        if (lane == 0) den_l = exs;
        if (sub == 0) {
            float2 f = __half22float2(*(const __half2*)(g_h2h + (size_t)gw * 16 + cl * 2));
            accA.x = exs * f.x;
            accA.y = exs * f.y;
        }
    }

    for (int j0 = start; j0 < end; j0 += 32) {
        int idx = j0 + lane;
        int s = (idx < end) ? g_srcl[idx] : 0;
        int cnt = min(32, end - j0);
        for (int t = 0; t < cnt; t += 8) {
            int iA = t + sub, iB = t + 4 + sub;
            int sA = __shfl_sync(0xffffffffu, s, iA);
            int sB = __shfl_sync(0xffffffffu, s, iB);
            if (iA < cnt) {
                float aA = __ldg(g_als2 + sA);
                float2 f = __half22float2(*(const __half2*)(g_h2h + (size_t)sA * 16 + cl * 2));
                float eA = __expf(lrelu(aA + ald) - m);
                if (cl == 0) den_l += eA;
                accA.x = fmaf(eA, f.x, accA.x);
                accA.y = fmaf(eA, f.y, accA.y);
            }
            if (iB < cnt) {
                float aB = __ldg(g_als2 + sB);
                float2 f = __half22float2(*(const __half2*)(g_h2h + (size_t)sB * 16 + cl * 2));
                float eB = __expf(lrelu(aB + ald) - m);
                if (cl == 0) den_l += eB;
                accB.x = fmaf(eB, f.x, accB.x);
                accB.y = fmaf(eB, f.y, accB.y);
            }
        }
    }
    accA.x += accB.x; accA.y += accB.y;
    accA.x += __shfl_xor_sync(0xffffffffu, accA.x, 8);
    accA.y += __shfl_xor_sync(0xffffffffu, accA.y, 8);
    accA.x += __shfl_xor_sync(0xffffffffu, accA.x, 16);
    accA.y += __shfl_xor_sync(0xffffffffu, accA.y, 16);
    den_l += __shfl_xor_sync(0xffffffffu, den_l, 8);
    den_l += __shfl_xor_sync(0xffffffffu, den_l, 16);
    float den = __shfl_sync(0xffffffffu, den_l, 0);

    float inv = 1.f / den;
    float v0 = accA.x * inv + b2[cl * 2];
    float v1 = accA.y * inv + b2[cl * 2 + 1];
    float mx = fmaxf(v0, v1);
#pragma unroll
    for (int o = 4; o >= 1; o >>= 1) mx = fmaxf(mx, __shfl_xor_sync(0xffffffffu, mx, o, 8));
    float s = __expf(v0 - mx) + __expf(v1 - mx);
#pragma unroll
    for (int o = 4; o >= 1; o >>= 1) s += __shfl_xor_sync(0xffffffffu, s, o, 8);
    if (sub == 0) {
        float ls = logf(s);
        float2 r = make_float2(v0 - mx - ls, v1 - mx - ls);
        *(float2*)(out + (size_t)gw * 16 + cl * 2) = r;
    }
}

// ---------------- launch ------------------------------------------------------
extern "C" void kernel_launch(void* const* d_in, const int* in_sizes, int n_in,
                              void* d_out, int out_size) {
    const float* x      = (const float*)d_in[0];
    const int*   ei     = (const int*)  d_in[1];
    const float* W1     = (const float*)d_in[2];
    const float* a_src1 = (const float*)d_in[3];
    const float* a_dst1 = (const float*)d_in[4];
    const float* b1     = (const float*)d_in[5];
    const float* W2     = (const float*)d_in[6];
    const float* a_src2 = (const float*)d_in[7];
    const float* a_dst2 = (const float*)d_in[8];
    const float* b2     = (const float*)d_in[9];
    float* out = (float*)d_out;

    const int smem1 = 2 * 128 * XSTR * sizeof(__half);   // 69632
    cudaFuncSetAttribute(k_gemm1h, cudaFuncAttributeMaxDynamicSharedMemorySize, smem1);

    k_gemm1h  <<<GB1 + 782, 256, smem1>>>(x, W1, a_src1, a_dst1, ei);
    k_scanA   <<<54, 1024>>>();
    k_scanBC  <<<196, 256>>>();
    k_scatter <<<782, 256>>>(ei);
    k_nodeagg1<<<6250, 256>>>(b1);
    k_gemm2   <<<3125, 256>>>(W2, a_src2, a_dst2);
    k_nodeagg2<<<6250, 256>>>(b2, out);
}

// round 9
// speedup vs baseline: 1.2037x; 1.1605x over previous
#include <cuda_runtime.h>
#include <cuda_fp16.h>
#include <math.h>

#define NN     50000
#define EE     800000
#define FIN    128
#define HID    32
#define HEADS  4
#define C1     128      // HEADS*HID
#define NCLS   16
#define NEG    0.2f
#define NEGINF_ORD 0x007FFFFFu   // f2o(-inf)

// ---------------- scratch (device globals; no allocation allowed) -----------
// NOTE: g_deg is zero on module load and re-zeroed by k_fincsr each call,
// so k_gemm1h's counting blocks can atomicAdd into it immediately.
__device__ __align__(16) __half   g_h1h [NN * C1];
__device__ __align__(16) float    g_als1[NN * HEADS];
__device__ __align__(16) float    g_ald1[NN * HEADS];
__device__ __align__(16) __half   g_h2h [NN * NCLS];
__device__ __align__(16) float    g_als2[NN];
__device__ __align__(16) float    g_ald2[NN];
__device__ __align__(16) unsigned g_maxu1[4];
__device__ __align__(16) unsigned g_maxu2[4];
__device__ __align__(16) int      g_deg   [NN];
__device__ __align__(16) int      g_rowloc[NN];      // block-local exclusive scan
__device__ __align__(16) int      g_rowfin[NN + 1];  // finalized rowptr
__device__ __align__(16) int      g_rank  [EE];
__device__ __align__(16) int      g_srcl  [EE];
__device__ __align__(16) int      g_btot  [64];

// ---------------- helpers ----------------------------------------------------
__device__ __forceinline__ float lrelu(float v) { return v > 0.f ? v : NEG * v; }

__device__ __forceinline__ unsigned f2o(float f) {
    unsigned u = __float_as_uint(f);
    return (u & 0x80000000u) ? ~u : (u | 0x80000000u);
}
__device__ __forceinline__ float o2f(unsigned u) {
    return (u & 0x80000000u) ? __uint_as_float(u & 0x7fffffffu)
                             : __uint_as_float(~u);
}

__device__ __forceinline__ void ldm_x4(unsigned& r0, unsigned& r1, unsigned& r2, unsigned& r3,
                                       unsigned addr) {
    asm volatile("ldmatrix.sync.aligned.m8n8.x4.shared.b16 {%0,%1,%2,%3}, [%4];"
                 : "=r"(r0), "=r"(r1), "=r"(r2), "=r"(r3) : "r"(addr));
}
__device__ __forceinline__ void ldm_x4t(unsigned& r0, unsigned& r1, unsigned& r2, unsigned& r3,
                                        unsigned addr) {
    asm volatile("ldmatrix.sync.aligned.m8n8.x4.trans.shared.b16 {%0,%1,%2,%3}, [%4];"
                 : "=r"(r0), "=r"(r1), "=r"(r2), "=r"(r3) : "r"(addr));
}
__device__ __forceinline__ void mma16816(float* c, const unsigned* a, unsigned b0, unsigned b1) {
    asm volatile("mma.sync.aligned.m16n8k16.row.col.f32.f16.f16.f32 "
                 "{%0,%1,%2,%3}, {%4,%5,%6,%7}, {%8,%9}, {%0,%1,%2,%3};"
                 : "+f"(c[0]), "+f"(c[1]), "+f"(c[2]), "+f"(c[3])
                 : "r"(a[0]), "r"(a[1]), "r"(a[2]), "r"(a[3]), "r"(b0), "r"(b1));
}

// ---------------- GEMM1 via HMMA + overlapped degree counting ----------------
// blocks [0,391): GEMM tile (128 nodes).  blocks [391,1173): count+rank x4.
#define XSTR 136   // padded half stride for conflict-free ldmatrix
#define GB1  391
__global__ void __launch_bounds__(256, 2) k_gemm1h(const float* __restrict__ x,
                        const float* __restrict__ W1,
                        const float* __restrict__ a_src, const float* __restrict__ a_dst,
                        const int* __restrict__ ei) {
    const int tid  = threadIdx.x;

    if (blockIdx.x >= GB1) {
        // degree counting + per-edge rank (g_deg pre-zeroed)
        int e0 = ((blockIdx.x - GB1) * 256 + tid) * 4;
        if (e0 < EE) {
            int4 d4 = *(const int4*)(ei + EE + e0);
            int4 r4;
            r4.x = atomicAdd(&g_deg[d4.x], 1);
            r4.y = atomicAdd(&g_deg[d4.y], 1);
            r4.z = atomicAdd(&g_deg[d4.z], 1);
            r4.w = atomicAdd(&g_deg[d4.w], 1);
            *(int4*)(g_rank + e0) = r4;
        }
        return;
    }

    // per-call init of the max cells (consumed by later launches)
    if (blockIdx.x == 0) {
        if (tid < 4)  g_maxu1[tid] = NEGINF_ORD;
        if (tid == 4) g_maxu2[0] = NEGINF_ORD;
    }

    extern __shared__ __half dsm[];
    __half* xs = dsm;                 // [128][XSTR]
    __half* ws = dsm + 128 * XSTR;    // [128][XSTR]

    const int lane = tid & 31;
    const int warp = tid >> 5;
    const int nb   = blockIdx.x * 128;
    const int g    = lane >> 2;
    const int tig  = lane & 3;

    for (int i = tid; i < 128 * 32; i += 256) {
        int r = i >> 5, q = i & 31;
        float4 v = (nb + r < NN) ? *(const float4*)(x + (size_t)(nb + r) * 128 + q * 4)
                                 : make_float4(0.f, 0.f, 0.f, 0.f);
        __half2* dst = (__half2*)(xs + r * XSTR + q * 4);
        dst[0] = __floats2half2_rn(v.x, v.y);
        dst[1] = __floats2half2_rn(v.z, v.w);
    }
    for (int i = tid; i < 128 * 32; i += 256) {
        int r = i >> 5, q = i & 31;
        float4 v = *(const float4*)(W1 + r * 128 + q * 4);
        __half2* dst = (__half2*)(ws + r * XSTR + q * 4);
        dst[0] = __floats2half2_rn(v.x, v.y);
        dst[1] = __floats2half2_rn(v.z, v.w);
    }
    __syncthreads();

    unsigned xs_u = (unsigned)__cvta_generic_to_shared(xs);
    unsigned ws_u = (unsigned)__cvta_generic_to_shared(ws);
    unsigned aaddr = xs_u + ((warp * 16 + (lane & 15)) * XSTR + (lane >> 4) * 8) * 2;
    unsigned baddr = ws_u + ((lane & 15) * XSTR + (lane >> 4) * 8) * 2;

    float c[16][4];
#pragma unroll
    for (int j = 0; j < 16; j++)
#pragma unroll
        for (int q = 0; q < 4; q++) c[j][q] = 0.f;

#pragma unroll
    for (int ks = 0; ks < 8; ks++) {
        unsigned a[4];
        ldm_x4(a[0], a[1], a[2], a[3], aaddr + ks * 32);
#pragma unroll
        for (int p = 0; p < 8; p++) {
            unsigned b0, b1, b2, b3;
            ldm_x4t(b0, b1, b2, b3, baddr + ks * (16 * XSTR * 2) + p * 32);
            mma16816(c[2 * p],     a, b0, b1);
            mma16816(c[2 * p + 1], a, b2, b3);
        }
    }

    int r0 = nb + warp * 16 + g;
    int r1 = r0 + 8;
    bool v0 = r0 < NN, v1 = r1 < NN;
    float ss0[4] = {0, 0, 0, 0}, sd0[4] = {0, 0, 0, 0};
    float ss1[4] = {0, 0, 0, 0}, sd1[4] = {0, 0, 0, 0};
#pragma unroll
    for (int j = 0; j < 16; j++) {
        int col = j * 8 + tig * 2;
        float a0 = a_src[col], a1 = a_src[col + 1];
        float d0 = a_dst[col], d1 = a_dst[col + 1];
        int h = j >> 2;
        ss0[h] += c[j][0] * a0 + c[j][1] * a1;
        sd0[h] += c[j][0] * d0 + c[j][1] * d1;
        ss1[h] += c[j][2] * a0 + c[j][3] * a1;
        sd1[h] += c[j][2] * d0 + c[j][3] * d1;
        if (v0) *(__half2*)(g_h1h + (size_t)r0 * 128 + col) = __floats2half2_rn(c[j][0], c[j][1]);
        if (v1) *(__half2*)(g_h1h + (size_t)r1 * 128 + col) = __floats2half2_rn(c[j][2], c[j][3]);
    }
#pragma unroll
    for (int o = 1; o <= 2; o <<= 1) {
#pragma unroll
        for (int h = 0; h < 4; h++) {
            ss0[h] += __shfl_xor_sync(0xffffffffu, ss0[h], o);
            sd0[h] += __shfl_xor_sync(0xffffffffu, sd0[h], o);
            ss1[h] += __shfl_xor_sync(0xffffffffu, ss1[h], o);
            sd1[h] += __shfl_xor_sync(0xffffffffu, sd1[h], o);
        }
    }
    if (tig == 0) {
        if (v0) {
#pragma unroll
            for (int h = 0; h < 4; h++) {
                g_als1[r0 * 4 + h] = ss0[h];
                g_ald1[r0 * 4 + h] = sd0[h];
            }
        }
        if (v1) {
#pragma unroll
            for (int h = 0; h < 4; h++) {
                g_als1[r1 * 4 + h] = ss1[h];
                g_ald1[r1 * 4 + h] = sd1[h];
            }
        }
    }
}

// ---------------- scanA: per-1024 local scan + als1 max-reduce ---------------
// blocks [0,49): scan (writes g_rowloc).  blocks [49,54): max over als1.
__global__ void k_scanA() {
    if (blockIdx.x >= 49) {
        int t = (blockIdx.x - 49) * 1024 + threadIdx.x;   // 5120 threads
        float m0 = -1e30f, m1 = -1e30f, m2 = -1e30f, m3 = -1e30f;
        for (int n = t; n < NN; n += 5120) {
            float4 a = *(const float4*)(g_als1 + n * 4);
            m0 = fmaxf(m0, a.x); m1 = fmaxf(m1, a.y);
            m2 = fmaxf(m2, a.z); m3 = fmaxf(m3, a.w);
        }
#pragma unroll
        for (int o = 16; o >= 1; o >>= 1) {
            m0 = fmaxf(m0, __shfl_xor_sync(0xffffffffu, m0, o));
            m1 = fmaxf(m1, __shfl_xor_sync(0xffffffffu, m1, o));
            m2 = fmaxf(m2, __shfl_xor_sync(0xffffffffu, m2, o));
            m3 = fmaxf(m3, __shfl_xor_sync(0xffffffffu, m3, o));
        }
        if ((threadIdx.x & 31) == 0) {
            atomicMax(&g_maxu1[0], f2o(m0));
            atomicMax(&g_maxu1[1], f2o(m1));
            atomicMax(&g_maxu1[2], f2o(m2));
            atomicMax(&g_maxu1[3], f2o(m3));
        }
        return;
    }
    __shared__ int sw[32];
    int t = threadIdx.x, b = blockIdx.x;
    int i = b * 1024 + t;
    int v = (i < NN) ? g_deg[i] : 0;
    int x = v;
#pragma unroll
    for (int o = 1; o < 32; o <<= 1) {
        int y = __shfl_up_sync(0xffffffffu, x, o);
        if ((t & 31) >= o) x += y;
    }
    if ((t & 31) == 31) sw[t >> 5] = x;
    __syncthreads();
    if (t < 32) {
        int y = sw[t];
#pragma unroll
        for (int o = 1; o < 32; o <<= 1) {
            int z = __shfl_up_sync(0xffffffffu, y, o);
            if (t >= o) y += z;
        }
        sw[t] = y;
    }
    __syncthreads();
    int off = (t >= 32) ? sw[(t >> 5) - 1] : 0;
    int incl = x + off;
    if (i < NN) g_rowloc[i] = incl - v;     // block-local exclusive
    if (t == 1023) g_btot[b] = incl;
}

// ---------------- fincsr: finalize rowptr + scatter (merged, race-free) ------
// Each of 782 blocks: (1) redundantly scans the 49 block totals, (2) writes
// g_rowfin for its 64-node slice + re-zeros g_deg, (3) scatters 1024 edges
// using g_rowloc (never written here) + boff + rank.
__global__ void __launch_bounds__(256) k_fincsr(const int* __restrict__ ei) {
    __shared__ int sh_boff[64];
    __shared__ int w0s;
    int t = threadIdx.x;
    int x = 0, v = 0;
    if (t < 64) {
        v = (t < 49) ? g_btot[t] : 0;
        x = v;
#pragma unroll
        for (int o = 1; o < 32; o <<= 1) {
            int y = __shfl_up_sync(0xffffffffu, x, o);
            if ((t & 31) >= o) x += y;
        }
        if (t == 31) w0s = x;
    }
    __syncthreads();
    if (t < 64) sh_boff[t] = (x + ((t >= 32) ? w0s : 0)) - v;
    __syncthreads();

    // finalize rowptr for this block's 64-node slice
    if (t < 64) {
        int i = blockIdx.x * 64 + t;
        if (i < NN) {
            g_rowfin[i] = g_rowloc[i] + sh_boff[i >> 10];
            g_deg[i] = 0;        // restore zeroed state for next call's count
        }
        if (i == NN) g_rowfin[NN] = EE;
    }

    // scatter 4 edges per thread
    int e0 = (blockIdx.x * 256 + t) * 4;
    if (e0 < EE) {
        int4 s4 = *(const int4*)(ei + e0);
        int4 d4 = *(const int4*)(ei + EE + e0);
        int4 r4 = *(const int4*)(g_rank + e0);
        int p0 = __ldg(&g_rowloc[d4.x]) + sh_boff[d4.x >> 10] + r4.x;
        int p1 = __ldg(&g_rowloc[d4.y]) + sh_boff[d4.y >> 10] + r4.y;
        int p2 = __ldg(&g_rowloc[d4.z]) + sh_boff[d4.z >> 10] + r4.z;
        int p3 = __ldg(&g_rowloc[d4.w]) + sh_boff[d4.w >> 10] + r4.w;
        g_srcl[p0] = s4.x;
        g_srcl[p1] = s4.y;
        g_srcl[p2] = s4.z;
        g_srcl[p3] = s4.w;
    }
}

// ---------------- layer-1 aggregation + fused layer-2 projection -------------
// warp per dst node; shfl-broadcast src ids; per-lane exp; then the SAME warp
// projects its act row through W2 (smem) -> h2h, als2/ald2, block max.
__global__ void __launch_bounds__(256) k_nodeagg1(const float* __restrict__ b1,
                        const float* __restrict__ W2, const float* __restrict__ a_src2,
                        const float* __restrict__ a_dst2) {
    __shared__ float w2s[2048];       // 8KB
    __shared__ float s_act[8][128];   // 4KB
    __shared__ float s_ps[8];
    const int tid = threadIdx.x;
    for (int i = tid; i < 2048; i += 256) w2s[i] = W2[i];
    __syncthreads();

    int wip  = tid >> 5;
    int gw   = (blockIdx.x * 256 + tid) >> 5;   // node id
    int lane = tid & 31;
    int sub  = lane >> 4;           // 2 edge slots
    int cl   = lane & 15;           // channel group: channels cl*8..cl*8+7
    int head = cl >> 2;

    float4 ald4 = *(const float4*)(g_ald1 + gw * 4);
    uint4 mu = *(const uint4*)g_maxu1;
    float ald_h = ((const float*)&ald4)[head];
    float m_h = lrelu(o2f(((const unsigned*)&mu)[head]) + ald_h);

    int start = g_rowfin[gw], end = g_rowfin[gw + 1];

    float den_l = 0.f;
    float accA[8], accB[8];
#pragma unroll
    for (int j = 0; j < 8; j++) { accA[j] = 0.f; accB[j] = 0.f; }

    // self loop
    {
        float a_h = __ldg(g_als1 + gw * 4 + head);
        float ex = __expf(lrelu(a_h + ald_h) - m_h);
        if (sub == 0 && (cl & 3) == 0) den_l = ex;
        if (sub == 0) {
            uint4 u = *(const uint4*)(g_h1h + (size_t)gw * 128 + cl * 8);
            const __half2* hp = (const __half2*)&u;
#pragma unroll
            for (int q = 0; q < 4; q++) {
                float2 f = __half22float2(hp[q]);
                accA[q * 2]     = ex * f.x;
                accA[q * 2 + 1] = ex * f.y;
            }
        }
    }

    for (int j0 = start; j0 < end; j0 += 32) {
        int idx = j0 + lane;
        int s = (idx < end) ? g_srcl[idx] : 0;
        int cnt = min(32, end - j0);
        for (int t = 0; t < cnt; t += 4) {
            int iA = t + sub, iB = t + 2 + sub;
            int sA = __shfl_sync(0xffffffffu, s, iA);
            int sB = __shfl_sync(0xffffffffu, s, iB);
            if (iA < cnt) {
                float aA = __ldg(g_als1 + sA * 4 + head);
                uint4 uA = *(const uint4*)(g_h1h + (size_t)sA * 128 + cl * 8);
                float eA = __expf(lrelu(aA + ald_h) - m_h);
                if ((cl & 3) == 0) den_l += eA;
                const __half2* hA = (const __half2*)&uA;
#pragma unroll
                for (int q = 0; q < 4; q++) {
                    float2 fA = __half22float2(hA[q]);
                    accA[q * 2]     = fmaf(eA, fA.x, accA[q * 2]);
                    accA[q * 2 + 1] = fmaf(eA, fA.y, accA[q * 2 + 1]);
                }
            }
            if (iB < cnt) {
                float aB = __ldg(g_als1 + sB * 4 + head);
                uint4 uB = *(const uint4*)(g_h1h + (size_t)sB * 128 + cl * 8);
                float eB = __expf(lrelu(aB + ald_h) - m_h);
                if ((cl & 3) == 0) den_l += eB;
                const __half2* hB = (const __half2*)&uB;
#pragma unroll
                for (int q = 0; q < 4; q++) {
                    float2 fB = __half22float2(hB[q]);
                    accB[q * 2]     = fmaf(eB, fB.x, accB[q * 2]);
                    accB[q * 2 + 1] = fmaf(eB, fB.y, accB[q * 2 + 1]);
                }
            }
        }
    }

#pragma unroll
    for (int j = 0; j < 8; j++) {
        accA[j] += accB[j];
        accA[j] += __shfl_xor_sync(0xffffffffu, accA[j], 16);
    }
    den_l += __shfl_xor_sync(0xffffffffu, den_l, 16);
    float den = __shfl_sync(0xffffffffu, den_l, cl & 12, 16);

    // act row (ELU) -> smem for this warp's node
    if (sub == 0) {
        float inv = 1.f / den;
        float4 ba = ((const float4*)b1)[cl * 2];
        float4 bb = ((const float4*)b1)[cl * 2 + 1];
        float4 r0, r1;
        r0.x = accA[0] * inv + ba.x;  r0.x = r0.x > 0.f ? r0.x : expm1f(r0.x);
        r0.y = accA[1] * inv + ba.y;  r0.y = r0.y > 0.f ? r0.y : expm1f(r0.y);
        r0.z = accA[2] * inv + ba.z;  r0.z = r0.z > 0.f ? r0.z : expm1f(r0.z);
        r0.w = accA[3] * inv + ba.w;  r0.w = r0.w > 0.f ? r0.w : expm1f(r0.w);
        r1.x = accA[4] * inv + bb.x;  r1.x = r1.x > 0.f ? r1.x : expm1f(r1.x);
        r1.y = accA[5] * inv + bb.y;  r1.y = r1.y > 0.f ? r1.y : expm1f(r1.y);
        r1.z = accA[6] * inv + bb.z;  r1.z = r1.z > 0.f ? r1.z : expm1f(r1.z);
        r1.w = accA[7] * inv + bb.w;  r1.w = r1.w > 0.f ? r1.w : expm1f(r1.w);
        *(float4*)&s_act[wip][cl * 8]     = r0;
        *(float4*)&s_act[wip][cl * 8 + 4] = r1;
    }
    __syncwarp();

    // fused projection: h2[c] = sum_k act[k] * W2[k][c]
    int c = lane & 15, hh = lane >> 4;   // hh = k-half
    const float* ar = &s_act[wip][hh * 64];
    float acc2 = 0.f;
#pragma unroll 16
    for (int k = 0; k < 64; k++)
        acc2 = fmaf(ar[k], w2s[(hh * 64 + k) * 16 + c], acc2);
    acc2 += __shfl_xor_sync(0xffffffffu, acc2, 16);
    if (sub == 0) g_h2h[(size_t)gw * 16 + c] = __float2half_rn(acc2);
    float ps = acc2 * a_src2[c], pd = acc2 * a_dst2[c];
#pragma unroll
    for (int o = 8; o >= 1; o >>= 1) {
        ps += __shfl_xor_sync(0xffffffffu, ps, o, 16);
        pd += __shfl_xor_sync(0xffffffffu, pd, o, 16);
    }
    if (lane == 0) {
        g_als2[gw] = ps;
        g_ald2[gw] = pd;
        s_ps[wip] = ps;
    }
    __syncthreads();
    if (tid == 0) {
        float m = s_ps[0];
#pragma unroll
        for (int i = 1; i < 8; i++) m = fmaxf(m, s_ps[i]);
        atomicMax(&g_maxu2[0], f2o(m));
    }
}

// ---------------- layer-2 fused aggregation + log_softmax --------------------
// shfl-broadcast src ids; per-lane exp; 16 edges per inner iter (4 chains).
__global__ void __launch_bounds__(256) k_nodeagg2(const float* __restrict__ b2,
                                                  float* __restrict__ out) {
    int gw   = (blockIdx.x * 256 + threadIdx.x) >> 5;
    int lane = threadIdx.x & 31;
    int sub  = lane >> 3, cl = lane & 7;

    float ald = g_ald2[gw];
    float m = lrelu(o2f(g_maxu2[0]) + ald);
    int start = g_rowfin[gw], end = g_rowfin[gw + 1];

    float2 accA = make_float2(0.f, 0.f), accB = make_float2(0.f, 0.f);
    float2 accC = make_float2(0.f, 0.f), accD = make_float2(0.f, 0.f);
    float den_l = 0.f;

    // self loop
    {
        float exs = __expf(lrelu(__ldg(g_als2 + gw) + ald) - m);
        if (lane == 0) den_l = exs;
        if (sub == 0) {
            float2 f = __half22float2(*(const __half2*)(g_h2h + (size_t)gw * 16 + cl * 2));
            accA.x = exs * f.x;
            accA.y = exs * f.y;
        }
    }

    for (int j0 = start; j0 < end; j0 += 32) {
        int idx = j0 + lane;
        int s = (idx < end) ? g_srcl[idx] : 0;
        int cnt = min(32, end - j0);
        for (int t = 0; t < cnt; t += 16) {
            int iA = t + sub, iB = t + 4 + sub, iC = t + 8 + sub, iD = t + 12 + sub;
            int sA = __shfl_sync(0xffffffffu, s, iA);
            int sB = __shfl_sync(0xffffffffu, s, iB);
            int sC = __shfl_sync(0xffffffffu, s, iC);
            int sD = __shfl_sync(0xffffffffu, s, iD);
            if (iA < cnt) {
                float aA = __ldg(g_als2 + sA);
                float2 f = __half22float2(*(const __half2*)(g_h2h + (size_t)sA * 16 + cl * 2));
                float eA = __expf(lrelu(aA + ald) - m);
                if (cl == 0) den_l += eA;
                accA.x = fmaf(eA, f.x, accA.x);
                accA.y = fmaf(eA, f.y, accA.y);
            }
            if (iB < cnt) {
                float aB = __ldg(g_als2 + sB);
                float2 f = __half22float2(*(const __half2*)(g_h2h + (size_t)sB * 16 + cl * 2));
                float eB = __expf(lrelu(aB + ald) - m);
                if (cl == 0) den_l += eB;
                accB.x = fmaf(eB, f.x, accB.x);
                accB.y = fmaf(eB, f.y, accB.y);
            }
            if (iC < cnt) {
                float aC = __ldg(g_als2 + sC);
                float2 f = __half22float2(*(const __half2*)(g_h2h + (size_t)sC * 16 + cl * 2));
                float eC = __expf(lrelu(aC + ald) - m);
                if (cl == 0) den_l += eC;
                accC.x = fmaf(eC, f.x, accC.x);
                accC.y = fmaf(eC, f.y, accC.y);
            }
            if (iD < cnt) {
                float aD = __ldg(g_als2 + sD);
                float2 f = __half22float2(*(const __half2*)(g_h2h + (size_t)sD * 16 + cl * 2));
                float eD = __expf(lrelu(aD + ald) - m);
                if (cl == 0) den_l += eD;
                accD.x = fmaf(eD, f.x, accD.x);
                accD.y = fmaf(eD, f.y, accD.y);
            }
        }
    }
    accA.x += accB.x + accC.x + accD.x;
    accA.y += accB.y + accC.y + accD.y;
    accA.x += __shfl_xor_sync(0xffffffffu, accA.x, 8);
    accA.y += __shfl_xor_sync(0xffffffffu, accA.y, 8);
    accA.x += __shfl_xor_sync(0xffffffffu, accA.x, 16);
    accA.y += __shfl_xor_sync(0xffffffffu, accA.y, 16);
    den_l += __shfl_xor_sync(0xffffffffu, den_l, 8);
    den_l += __shfl_xor_sync(0xffffffffu, den_l, 16);
    float den = __shfl_sync(0xffffffffu, den_l, 0);

    float inv = 1.f / den;
    float v0 = accA.x * inv + b2[cl * 2];
    float v1 = accA.y * inv + b2[cl * 2 + 1];
    float mx = fmaxf(v0, v1);
#pragma unroll
    for (int o = 4; o >= 1; o >>= 1) mx = fmaxf(mx, __shfl_xor_sync(0xffffffffu, mx, o, 8));
    float s = __expf(v0 - mx) + __expf(v1 - mx);
#pragma unroll
    for (int o = 4; o >= 1; o >>= 1) s += __shfl_xor_sync(0xffffffffu, s, o, 8);
    if (sub == 0) {
        float ls = logf(s);
        float2 r = make_float2(v0 - mx - ls, v1 - mx - ls);
        *(float2*)(out + (size_t)gw * 16 + cl * 2) = r;
    }
}

// ---------------- launch ------------------------------------------------------
extern "C" void kernel_launch(void* const* d_in, const int* in_sizes, int n_in,
                              void* d_out, int out_size) {
    const float* x      = (const float*)d_in[0];
    const int*   ei     = (const int*)  d_in[1];
    const float* W1     = (const float*)d_in[2];
    const float* a_src1 = (const float*)d_in[3];
    const float* a_dst1 = (const float*)d_in[4];
    const float* b1     = (const float*)d_in[5];
    const float* W2     = (const float*)d_in[6];
    const float* a_src2 = (const float*)d_in[7];
    const float* a_dst2 = (const float*)d_in[8];
    const float* b2     = (const float*)d_in[9];
    float* out = (float*)d_out;

    const int smem1 = 2 * 128 * XSTR * sizeof(__half);   // 69632
    cudaFuncSetAttribute(k_gemm1h, cudaFuncAttributeMaxDynamicSharedMemorySize, smem1);

    k_gemm1h  <<<GB1 + 782, 256, smem1>>>(x, W1, a_src1, a_dst1, ei);
    k_scanA   <<<54, 1024>>>();
    k_fincsr  <<<782, 256>>>(ei);
    k_nodeagg1<<<6250, 256>>>(b1, W2, a_src2, a_dst2);
    k_nodeagg2<<<6250, 256>>>(b2, out);
}